// round 6
// baseline (speedup 1.0000x reference)
#include <cuda_runtime.h>
#include <math.h>

#define NN 50000
#define DD 64
#define EE 1250000
#define BB 4096
#define ROW4 16              // float4 per embedding row

typedef unsigned long long u64;

// ---------------- scratch (device globals; no allocation) ----------------
__device__ float g_embA[NN * DD];
__device__ float g_embB[NN * DD];
__device__ float g_agg [NN * DD];
__device__ float g_ue[BB * 256];
__device__ float g_pe[BB * 256];
__device__ float g_ne[BB * 256];

// ---------------- packed fp32x2 helpers (Blackwell) ----------------
__device__ __forceinline__ u64 fma2(u64 a, u64 b, u64 c) {
    u64 d;
    asm("fma.rn.f32x2 %0, %1, %2, %3;" : "=l"(d) : "l"(a), "l"(b), "l"(c));
    return d;
}
__device__ __forceinline__ u64 add2(u64 a, u64 b) {
    u64 d;
    asm("add.rn.f32x2 %0, %1, %2;" : "=l"(d) : "l"(a), "l"(b));
    return d;
}
__device__ __forceinline__ u64 dup2(float x) {
    u64 d; unsigned b = __float_as_uint(x);
    asm("mov.b64 %0, {%1, %1};" : "=l"(d) : "r"(b));
    return d;
}
__device__ __forceinline__ void unpack2(float& lo, float& hi, u64 v) {
    unsigned a, b;
    asm("mov.b64 {%0, %1}, %2;" : "=r"(a), "=r"(b) : "l"(v));
    lo = __uint_as_float(a); hi = __uint_as_float(b);
}

// ---------------- kernels ----------------

__global__ void zero_agg_kernel() {
    int i = blockIdx.x * blockDim.x + threadIdx.x;
    if (i < NN * DD / 4)
        reinterpret_cast<float4*>(g_agg)[i] = make_float4(0.f, 0.f, 0.f, 0.f);
}

// 16 threads per edge; each handles one float4 chunk of the 64-wide row.
// Scatter via vector red (one L2 atomic transaction per 16B).
__global__ void spmm_kernel(const float* __restrict__ emb,
                            const float* __restrict__ vals,
                            const int*  __restrict__ rows,
                            const int*  __restrict__ cols) {
    unsigned gid = blockIdx.x * blockDim.x + threadIdx.x;
    unsigned e = gid >> 4;
    unsigned c = gid & 15u;
    if (e >= EE) return;
    int col = cols[e];
    int row = rows[e];
    float v = vals[e];
    float4 x = reinterpret_cast<const float4*>(emb)[(size_t)col * ROW4 + c];
    float4* dst = reinterpret_cast<float4*>(g_agg) + (size_t)row * ROW4 + c;
    asm volatile("red.global.add.v4.f32 [%0], {%1,%2,%3,%4};"
                 :: "l"(dst), "f"(v * x.x), "f"(v * x.y), "f"(v * x.z), "f"(v * x.w)
                 : "memory");
}

// ---------------- fused dense layer (register-blocked GEMM) ----------------
//   sx = (agg+emb) @ W1^T + b1
//   ox = agg * (emb @ W2^T + b2)
//   out = leaky_relu(sx + ox, 0.01)
// Block: 128 nodes x 64 outputs, 256 threads, 4x8 thread tile, f32x2 FMA.
#define BM 128
#define XT_S 132                 // smem stride (floats) for transposed X/AGG
#define W_S  68                  // smem stride (floats) for transposed W
#define OFF_XT 0
#define OFF_AT (64 * XT_S)                    // 8448
#define OFF_W1 (2 * 64 * XT_S)                // 16896
#define OFF_W2 (OFF_W1 + 64 * W_S)            // 21248
#define OFF_B1 (OFF_W2 + 64 * W_S)            // 25600
#define OFF_B2 (OFF_B1 + 64)
#define DSM_FLOATS (OFF_B2 + 64)              // 25728 floats = 102912 B

__global__ void __launch_bounds__(256, 2) dense_kernel(
        const float* __restrict__ src,
        const float* __restrict__ w1,
        const float* __restrict__ b1,
        const float* __restrict__ w2,
        const float* __restrict__ b2,
        float* __restrict__ dst) {
    extern __shared__ float sm[];
    float* sXT = sm + OFF_XT;
    float* sAT = sm + OFF_AT;
    float* sW1 = sm + OFF_W1;
    float* sW2 = sm + OFF_W2;
    float* sB1 = sm + OFF_B1;
    float* sB2 = sm + OFF_B2;

    const int tid = threadIdx.x;
    const int base = blockIdx.x * BM;
    const int nrows = min(BM, NN - base);

    // ---- stage W1/W2 transposed [k][j] ----
    {
        const float4* w1v = reinterpret_cast<const float4*>(w1);
        const float4* w2v = reinterpret_cast<const float4*>(w2);
        for (int i = tid; i < DD * ROW4; i += 256) {
            int j = i >> 4, c = i & 15;
            float4 a = w1v[j * ROW4 + c];
            float4 b = w2v[j * ROW4 + c];
            int k0 = 4 * c;
            sW1[(k0 + 0) * W_S + j] = a.x; sW1[(k0 + 1) * W_S + j] = a.y;
            sW1[(k0 + 2) * W_S + j] = a.z; sW1[(k0 + 3) * W_S + j] = a.w;
            sW2[(k0 + 0) * W_S + j] = b.x; sW2[(k0 + 1) * W_S + j] = b.y;
            sW2[(k0 + 2) * W_S + j] = b.z; sW2[(k0 + 3) * W_S + j] = b.w;
        }
        if (tid < DD) { sB1[tid] = b1[tid]; sB2[tid] = b2[tid]; }
    }
    // ---- stage X/AGG transposed [k][n] (zero-pad tail rows) ----
    {
        const float4* srcv = reinterpret_cast<const float4*>(src);
        const float4* aggv = reinterpret_cast<const float4*>(g_agg);
        for (int i = tid; i < BM * ROW4; i += 256) {
            int n = i >> 4, c = i & 15;
            float4 xv = make_float4(0.f, 0.f, 0.f, 0.f);
            float4 av = xv;
            if (n < nrows) {
                xv = srcv[(size_t)(base + n) * ROW4 + c];
                av = aggv[(size_t)(base + n) * ROW4 + c];
            }
            int k0 = 4 * c;
            sXT[(k0 + 0) * XT_S + n] = xv.x; sXT[(k0 + 1) * XT_S + n] = xv.y;
            sXT[(k0 + 2) * XT_S + n] = xv.z; sXT[(k0 + 3) * XT_S + n] = xv.w;
            sAT[(k0 + 0) * XT_S + n] = av.x; sAT[(k0 + 1) * XT_S + n] = av.y;
            sAT[(k0 + 2) * XT_S + n] = av.z; sAT[(k0 + 3) * XT_S + n] = av.w;
        }
    }
    __syncthreads();

    const int tn = tid & 7;        // j0 = tn*8
    const int tm = tid >> 3;       // n0 = tm*4
    const int j0 = tn * 8;
    const int n0 = tm * 4;

    u64 c1[4][4], c2[4][4];
#pragma unroll
    for (int m = 0; m < 4; m++)
#pragma unroll
        for (int p = 0; p < 4; p++) { c1[m][p] = 0; c2[m][p] = 0; }

    const ulonglong2* sXTu = reinterpret_cast<const ulonglong2*>(sXT);
    const ulonglong2* sATu = reinterpret_cast<const ulonglong2*>(sAT);
    const ulonglong2* sW1u = reinterpret_cast<const ulonglong2*>(sW1);
    const ulonglong2* sW2u = reinterpret_cast<const ulonglong2*>(sW2);

#pragma unroll 4
    for (int k = 0; k < DD; k++) {
        ulonglong2 xu = sXTu[k * (XT_S / 4) + tm];
        ulonglong2 au = sATu[k * (XT_S / 4) + tm];
        u64 axp0 = add2(xu.x, au.x);
        u64 axp1 = add2(xu.y, au.y);
        float x0, x1, x2, x3, a0, a1, a2, a3;
        unpack2(x0, x1, xu.x);  unpack2(x2, x3, xu.y);
        unpack2(a0, a1, axp0);  unpack2(a2, a3, axp1);
        u64 dx[4] = { dup2(x0), dup2(x1), dup2(x2), dup2(x3) };
        u64 da[4] = { dup2(a0), dup2(a1), dup2(a2), dup2(a3) };

        ulonglong2 w1u0 = sW1u[k * (W_S / 4) + 2 * tn];
        ulonglong2 w1u1 = sW1u[k * (W_S / 4) + 2 * tn + 1];
        ulonglong2 w2u0 = sW2u[k * (W_S / 4) + 2 * tn];
        ulonglong2 w2u1 = sW2u[k * (W_S / 4) + 2 * tn + 1];
#pragma unroll
        for (int m = 0; m < 4; m++) {
            c1[m][0] = fma2(da[m], w1u0.x, c1[m][0]);
            c1[m][1] = fma2(da[m], w1u0.y, c1[m][1]);
            c1[m][2] = fma2(da[m], w1u1.x, c1[m][2]);
            c1[m][3] = fma2(da[m], w1u1.y, c1[m][3]);
            c2[m][0] = fma2(dx[m], w2u0.x, c2[m][0]);
            c2[m][1] = fma2(dx[m], w2u0.y, c2[m][1]);
            c2[m][2] = fma2(dx[m], w2u1.x, c2[m][2]);
            c2[m][3] = fma2(dx[m], w2u1.y, c2[m][3]);
        }
    }

    // ---- epilogue: agg frag from sAT, bias, elementwise, leaky, store ----
    const float4* sAT4 = reinterpret_cast<const float4*>(sAT);
    float4 agf[8];
#pragma unroll
    for (int jn = 0; jn < 8; jn++)
        agf[jn] = sAT4[(j0 + jn) * (XT_S / 4) + tm];   // agg[n0..n0+3][j0+jn]

    float bb1[8], bb2[8];
#pragma unroll
    for (int jn = 0; jn < 8; jn++) { bb1[jn] = sB1[j0 + jn]; bb2[jn] = sB2[j0 + jn]; }

    float4* dstv = reinterpret_cast<float4*>(dst);
#pragma unroll
    for (int m = 0; m < 4; m++) {
        if (n0 + m >= nrows) break;
        float o[8];
#pragma unroll
        for (int p = 0; p < 4; p++) {
            float s1a, s1b, s2a, s2b;
            unpack2(s1a, s1b, c1[m][p]);
            unpack2(s2a, s2b, c2[m][p]);
            int ja = 2 * p, jb = 2 * p + 1;
            float aga = (m == 0) ? agf[ja].x : (m == 1) ? agf[ja].y : (m == 2) ? agf[ja].z : agf[ja].w;
            float agb = (m == 0) ? agf[jb].x : (m == 1) ? agf[jb].y : (m == 2) ? agf[jb].z : agf[jb].w;
            float va = (s1a + bb1[ja]) + aga * (s2a + bb2[ja]);
            float vb = (s1b + bb1[jb]) + agb * (s2b + bb2[jb]);
            o[ja] = va > 0.f ? va : 0.01f * va;
            o[jb] = vb > 0.f ? vb : 0.01f * vb;
        }
        size_t rb = (size_t)(base + n0 + m) * ROW4 + tn * 2;
        dstv[rb]     = make_float4(o[0], o[1], o[2], o[3]);
        dstv[rb + 1] = make_float4(o[4], o[5], o[6], o[7]);
    }
}

// ---------------- gather + loss ----------------

__global__ void gather_kernel(const float* __restrict__ emb,
                              const int* __restrict__ user,
                              const int* __restrict__ pos,
                              const int* __restrict__ neg,
                              int layer) {
    unsigned t = blockIdx.x * blockDim.x + threadIdx.x;
    if (t >= BB * 16) return;
    unsigned i = t >> 4;
    unsigned c = t & 15u;
    unsigned doff = i * 64 + (unsigned)layer * 16 + c;
    const float4* ev = reinterpret_cast<const float4*>(emb);
    reinterpret_cast<float4*>(g_ue)[doff] = ev[(size_t)user[i] * ROW4 + c];
    reinterpret_cast<float4*>(g_pe)[doff] = ev[(size_t)pos [i] * ROW4 + c];
    reinterpret_cast<float4*>(g_ne)[doff] = ev[(size_t)neg [i] * ROW4 + c];
}

__global__ void zero_out_kernel(float* out) {
    if (threadIdx.x == 0 && blockIdx.x == 0) out[0] = 0.f;
}

__global__ void loss_kernel(float* __restrict__ out) {
    int i = blockIdx.x * blockDim.x + threadIdx.x;
    float dp = 0.f, dn = 0.f;
    if (i < BB) {
        const float4* uv = reinterpret_cast<const float4*>(g_ue);
        const float4* pv = reinterpret_cast<const float4*>(g_pe);
        const float4* nv = reinterpret_cast<const float4*>(g_ne);
#pragma unroll 8
        for (int c = 0; c < 64; c++) {
            float4 u = uv[(size_t)i * 64 + c];
            float4 p = pv[(size_t)i * 64 + c];
            float4 q = nv[(size_t)i * 64 + c];
            dp += u.x*p.x + u.y*p.y + u.z*p.z + u.w*p.w;
            dn += u.x*q.x + u.y*q.y + u.z*q.z + u.w*q.w;
        }
    }
    float d = dp - dn;
    float l = (i < BB) ? (fmaxf(-d, 0.f) + log1pf(expf(-fabsf(d)))) : 0.f;

    __shared__ float red[256];
    red[threadIdx.x] = l;
    __syncthreads();
    for (int s = 128; s > 0; s >>= 1) {
        if (threadIdx.x < s) red[threadIdx.x] += red[threadIdx.x + s];
        __syncthreads();
    }
    if (threadIdx.x == 0) atomicAdd(out, red[0]);
}

// ---------------- launch ----------------

extern "C" void kernel_launch(void* const* d_in, const int* in_sizes, int n_in,
                              void* d_out, int out_size) {
    const float* emb  = (const float*)d_in[0];
    const float* w1w  = (const float*)d_in[1];
    const float* w1b  = (const float*)d_in[2];
    const float* w2w  = (const float*)d_in[3];
    const float* w2b  = (const float*)d_in[4];
    const float* vals = (const float*)d_in[5];
    const int*   rows = (const int*)d_in[6];
    const int*   cols = (const int*)d_in[7];
    const int*   user = (const int*)d_in[8];
    const int*   pos  = (const int*)d_in[9];
    const int*   neg  = (const int*)d_in[10];
    float* out = (float*)d_out;

    void *pA = nullptr, *pB = nullptr;
    cudaGetSymbolAddress(&pA, g_embA);
    cudaGetSymbolAddress(&pB, g_embB);
    float* eA = (float*)pA;
    float* eB = (float*)pB;

    const int SMEM_BYTES = DSM_FLOATS * 4;   // 102912
    cudaFuncSetAttribute(dense_kernel,
                         cudaFuncAttributeMaxDynamicSharedMemorySize, SMEM_BYTES);

    const int ZB = (NN * DD / 4 + 255) / 256;
    const int SB = (EE * 16) / 256;           // 78125 exact
    const int DB = (NN + BM - 1) / BM;        // 391
    const int GB = (BB * 16 + 255) / 256;

    // layer 0 input gather
    gather_kernel<<<GB, 256>>>(emb, user, pos, neg, 0);

    // layer 1: emb -> eA
    zero_agg_kernel<<<ZB, 256>>>();
    spmm_kernel<<<SB, 256>>>(emb, vals, rows, cols);
    dense_kernel<<<DB, 256, SMEM_BYTES>>>(emb, w1w, w1b, w2w, w2b, eA);
    gather_kernel<<<GB, 256>>>(eA, user, pos, neg, 1);

    // layer 2: eA -> eB
    zero_agg_kernel<<<ZB, 256>>>();
    spmm_kernel<<<SB, 256>>>(eA, vals, rows, cols);
    dense_kernel<<<DB, 256, SMEM_BYTES>>>(eA, w1w + 4096, w1b + 64, w2w + 4096, w2b + 64, eB);
    gather_kernel<<<GB, 256>>>(eB, user, pos, neg, 2);

    // layer 3: eB -> eA
    zero_agg_kernel<<<ZB, 256>>>();
    spmm_kernel<<<SB, 256>>>(eB, vals, rows, cols);
    dense_kernel<<<DB, 256, SMEM_BYTES>>>(eB, w1w + 8192, w1b + 128, w2w + 8192, w2b + 128, eA);
    gather_kernel<<<GB, 256>>>(eA, user, pos, neg, 3);

    // loss
    zero_out_kernel<<<1, 32>>>(out);
    loss_kernel<<<BB / 256, 256>>>(out);
}

// round 7
// speedup vs baseline: 1.0243x; 1.0243x over previous
#include <cuda_runtime.h>
#include <math.h>

#define NN 50000
#define DD 64
#define EE 1250000
#define BB 4096
#define ROW4 16              // float4 per embedding row

typedef unsigned long long u64;

// ---------------- scratch (device globals; no allocation) ----------------
__device__ float g_embA[NN * DD];
__device__ float g_embB[NN * DD];
__device__ float g_agg [NN * DD];
__device__ float g_ue[BB * 256];
__device__ float g_pe[BB * 256];
__device__ float g_ne[BB * 256];

// ---------------- packed fp32x2 helpers (Blackwell) ----------------
__device__ __forceinline__ u64 fma2(u64 a, u64 b, u64 c) {
    u64 d;
    asm("fma.rn.f32x2 %0, %1, %2, %3;" : "=l"(d) : "l"(a), "l"(b), "l"(c));
    return d;
}
__device__ __forceinline__ void unpack2(float& lo, float& hi, u64 v) {
    unsigned a, b;
    asm("mov.b64 {%0, %1}, %2;" : "=r"(a), "=r"(b) : "l"(v));
    lo = __uint_as_float(a); hi = __uint_as_float(b);
}

// ---------------- kernels ----------------

__global__ void zero_agg_kernel() {
    int i = blockIdx.x * blockDim.x + threadIdx.x;
    if (i < NN * DD / 4)
        reinterpret_cast<float4*>(g_agg)[i] = make_float4(0.f, 0.f, 0.f, 0.f);
}

// 16 threads per edge; one float4 chunk per thread; vector red scatter.
__global__ void spmm_kernel(const float* __restrict__ emb,
                            const float* __restrict__ vals,
                            const int*  __restrict__ rows,
                            const int*  __restrict__ cols) {
    unsigned gid = blockIdx.x * blockDim.x + threadIdx.x;
    unsigned e = gid >> 4;
    unsigned c = gid & 15u;
    if (e >= EE) return;
    int col = cols[e];
    int row = rows[e];
    float v = vals[e];
    float4 x = reinterpret_cast<const float4*>(emb)[(size_t)col * ROW4 + c];
    float4* dst = reinterpret_cast<float4*>(g_agg) + (size_t)row * ROW4 + c;
    asm volatile("red.global.add.v4.f32 [%0], {%1,%2,%3,%4};"
                 :: "l"(dst), "f"(v * x.x), "f"(v * x.y), "f"(v * x.z), "f"(v * x.w)
                 : "memory");
}

// ---------------- fused dense layer (pair-vectorized GEMM) ----------------
//   sx = (agg+emb) @ W1^T + b1
//   ox = agg * (emb @ W2^T + b2)
//   out = leaky_relu(sx + ox, 0.01)
// Block = 128 nodes x 64 outputs, 256 threads.
// Thread tile: 8 nodes (4 f32x2 node-pairs) x 4 outputs, both GEMMs.
// smem: X[k][n], AX[k][n] (pre-added), W1d/W2d[k][2j] duplicated pairs.
// Inner loop: 12 LDS + 32 fma2 per k, ZERO mov/alu.
#define BM 128
#define XS 132                                 // row stride (floats), 8B-aligned
#define OFF_X  0
#define OFF_AX (64 * XS)                       // 8448
#define OFF_W1 (2 * 64 * XS)                   // 16896
#define OFF_W2 (3 * 64 * XS)                   // 25344
#define OFF_B1 (4 * 64 * XS)                   // 33792
#define OFF_B2 (OFF_B1 + 64)
#define DSM_FLOATS (OFF_B2 + 64)               // 33920 floats = 135680 B

__global__ void __launch_bounds__(256, 1) dense_kernel(
        const float* __restrict__ src,
        const float* __restrict__ w1,
        const float* __restrict__ b1,
        const float* __restrict__ w2,
        const float* __restrict__ b2,
        float* __restrict__ dst) {
    extern __shared__ float sm[];
    float* sX  = sm + OFF_X;
    float* sAX = sm + OFF_AX;
    float* sW1 = sm + OFF_W1;
    float* sW2 = sm + OFF_W2;
    float* sB1 = sm + OFF_B1;
    float* sB2 = sm + OFF_B2;

    const int tid = threadIdx.x;
    const int base = blockIdx.x * BM;
    const int nrows = min(BM, NN - base);

    // ---- stage W1/W2 transposed+duplicated: sW[k][2j] = sW[k][2j+1] = w[j][k]
    {
        const float4* w1v = reinterpret_cast<const float4*>(w1);
        const float4* w2v = reinterpret_cast<const float4*>(w2);
        for (int i = tid; i < DD * ROW4; i += 256) {
            int j = i >> 4, c = i & 15;
            float4 a = w1v[j * ROW4 + c];
            float4 b = w2v[j * ROW4 + c];
            int k0 = 4 * c;
            sW1[(k0 + 0) * XS + 2 * j] = a.x; sW1[(k0 + 0) * XS + 2 * j + 1] = a.x;
            sW1[(k0 + 1) * XS + 2 * j] = a.y; sW1[(k0 + 1) * XS + 2 * j + 1] = a.y;
            sW1[(k0 + 2) * XS + 2 * j] = a.z; sW1[(k0 + 2) * XS + 2 * j + 1] = a.z;
            sW1[(k0 + 3) * XS + 2 * j] = a.w; sW1[(k0 + 3) * XS + 2 * j + 1] = a.w;
            sW2[(k0 + 0) * XS + 2 * j] = b.x; sW2[(k0 + 0) * XS + 2 * j + 1] = b.x;
            sW2[(k0 + 1) * XS + 2 * j] = b.y; sW2[(k0 + 1) * XS + 2 * j + 1] = b.y;
            sW2[(k0 + 2) * XS + 2 * j] = b.z; sW2[(k0 + 2) * XS + 2 * j + 1] = b.z;
            sW2[(k0 + 3) * XS + 2 * j] = b.w; sW2[(k0 + 3) * XS + 2 * j + 1] = b.w;
        }
        if (tid < DD) { sB1[tid] = b1[tid]; sB2[tid] = b2[tid]; }
    }
    // ---- stage X / AX=X+AGG transposed [k][n] (zero-pad tail rows) ----
    {
        const float4* srcv = reinterpret_cast<const float4*>(src);
        const float4* aggv = reinterpret_cast<const float4*>(g_agg);
        for (int i = tid; i < BM * ROW4; i += 256) {
            int n = i >> 4, c = i & 15;
            float4 xv = make_float4(0.f, 0.f, 0.f, 0.f);
            float4 av = xv;
            if (n < nrows) {
                xv = srcv[(size_t)(base + n) * ROW4 + c];
                av = aggv[(size_t)(base + n) * ROW4 + c];
            }
            int k0 = 4 * c;
            sX [(k0 + 0) * XS + n] = xv.x;        sX [(k0 + 1) * XS + n] = xv.y;
            sX [(k0 + 2) * XS + n] = xv.z;        sX [(k0 + 3) * XS + n] = xv.w;
            sAX[(k0 + 0) * XS + n] = xv.x + av.x; sAX[(k0 + 1) * XS + n] = xv.y + av.y;
            sAX[(k0 + 2) * XS + n] = xv.z + av.z; sAX[(k0 + 3) * XS + n] = xv.w + av.w;
        }
    }
    __syncthreads();

    // thread mapping: lane 0-15 / 16-31 split on j, node pairs strided by 32
    const int lane = tid & 31;
    const int tm = lane & 15;                  // node pair base: n = tm*2 + i*32
    const int tj = (tid >> 5) * 2 + (lane >> 4);  // 0..15 -> j0 = tj*4
    const int j0 = tj * 4;
    const int nb = tm * 2;

    u64 c1[4][4], c2[4][4];
#pragma unroll
    for (int i = 0; i < 4; i++)
#pragma unroll
        for (int p = 0; p < 4; p++) { c1[i][p] = 0; c2[i][p] = 0; }

    const float* xp  = sX  + nb;
    const float* ap  = sAX + nb;
    const float* w1p = sW1 + 2 * j0;
    const float* w2p = sW2 + 2 * j0;

#pragma unroll 4
    for (int k = 0; k < DD; k++) {
        const int ko = k * XS;
        u64 dx0 = *reinterpret_cast<const u64*>(xp + ko);
        u64 dx1 = *reinterpret_cast<const u64*>(xp + ko + 32);
        u64 dx2 = *reinterpret_cast<const u64*>(xp + ko + 64);
        u64 dx3 = *reinterpret_cast<const u64*>(xp + ko + 96);
        u64 da0 = *reinterpret_cast<const u64*>(ap + ko);
        u64 da1 = *reinterpret_cast<const u64*>(ap + ko + 32);
        u64 da2 = *reinterpret_cast<const u64*>(ap + ko + 64);
        u64 da3 = *reinterpret_cast<const u64*>(ap + ko + 96);
        ulonglong2 w1a = *reinterpret_cast<const ulonglong2*>(w1p + ko);
        ulonglong2 w1b = *reinterpret_cast<const ulonglong2*>(w1p + ko + 4);
        ulonglong2 w2a = *reinterpret_cast<const ulonglong2*>(w2p + ko);
        ulonglong2 w2b = *reinterpret_cast<const ulonglong2*>(w2p + ko + 4);

        c1[0][0] = fma2(da0, w1a.x, c1[0][0]); c1[0][1] = fma2(da0, w1a.y, c1[0][1]);
        c1[0][2] = fma2(da0, w1b.x, c1[0][2]); c1[0][3] = fma2(da0, w1b.y, c1[0][3]);
        c1[1][0] = fma2(da1, w1a.x, c1[1][0]); c1[1][1] = fma2(da1, w1a.y, c1[1][1]);
        c1[1][2] = fma2(da1, w1b.x, c1[1][2]); c1[1][3] = fma2(da1, w1b.y, c1[1][3]);
        c1[2][0] = fma2(da2, w1a.x, c1[2][0]); c1[2][1] = fma2(da2, w1a.y, c1[2][1]);
        c1[2][2] = fma2(da2, w1b.x, c1[2][2]); c1[2][3] = fma2(da2, w1b.y, c1[2][3]);
        c1[3][0] = fma2(da3, w1a.x, c1[3][0]); c1[3][1] = fma2(da3, w1a.y, c1[3][1]);
        c1[3][2] = fma2(da3, w1b.x, c1[3][2]); c1[3][3] = fma2(da3, w1b.y, c1[3][3]);
        c2[0][0] = fma2(dx0, w2a.x, c2[0][0]); c2[0][1] = fma2(dx0, w2a.y, c2[0][1]);
        c2[0][2] = fma2(dx0, w2b.x, c2[0][2]); c2[0][3] = fma2(dx0, w2b.y, c2[0][3]);
        c2[1][0] = fma2(dx1, w2a.x, c2[1][0]); c2[1][1] = fma2(dx1, w2a.y, c2[1][1]);
        c2[1][2] = fma2(dx1, w2b.x, c2[1][2]); c2[1][3] = fma2(dx1, w2b.y, c2[1][3]);
        c2[2][0] = fma2(dx2, w2a.x, c2[2][0]); c2[2][1] = fma2(dx2, w2a.y, c2[2][1]);
        c2[2][2] = fma2(dx2, w2b.x, c2[2][2]); c2[2][3] = fma2(dx2, w2b.y, c2[2][3]);
        c2[3][0] = fma2(dx3, w2a.x, c2[3][0]); c2[3][1] = fma2(dx3, w2a.y, c2[3][1]);
        c2[3][2] = fma2(dx3, w2b.x, c2[3][2]); c2[3][3] = fma2(dx3, w2b.y, c2[3][3]);
    }

    // ---- epilogue: bias, agg (= AX - X) elementwise, leaky-relu, store ----
    float bb1[4], bb2[4];
#pragma unroll
    for (int p = 0; p < 4; p++) { bb1[p] = sB1[j0 + p]; bb2[p] = sB2[j0 + p]; }

#pragma unroll
    for (int i = 0; i < 4; i++) {
        int n = nb + i * 32;
        if (n >= nrows) break;
        float oa[4], ob[4];
#pragma unroll
        for (int p = 0; p < 4; p++) {
            float s1a, s1b, s2a, s2b;
            unpack2(s1a, s1b, c1[i][p]);
            unpack2(s2a, s2b, c2[i][p]);
            int jj = (j0 + p) * XS;
            float aga = sAX[jj + n]     - sX[jj + n];
            float agb = sAX[jj + n + 1] - sX[jj + n + 1];
            float va = (s1a + bb1[p]) + aga * (s2a + bb2[p]);
            float vb = (s1b + bb1[p]) + agb * (s2b + bb2[p]);
            oa[p] = va > 0.f ? va : 0.01f * va;
            ob[p] = vb > 0.f ? vb : 0.01f * vb;
        }
        float4* dstv = reinterpret_cast<float4*>(dst + (size_t)(base + n) * DD + j0);
        dstv[0] = make_float4(oa[0], oa[1], oa[2], oa[3]);
        if (n + 1 < nrows)
            *reinterpret_cast<float4*>(dst + (size_t)(base + n + 1) * DD + j0) =
                make_float4(ob[0], ob[1], ob[2], ob[3]);
    }
}

// ---------------- gather + loss ----------------

__global__ void gather_kernel(const float* __restrict__ emb,
                              const int* __restrict__ user,
                              const int* __restrict__ pos,
                              const int* __restrict__ neg,
                              int layer) {
    unsigned t = blockIdx.x * blockDim.x + threadIdx.x;
    if (t >= BB * 16) return;
    unsigned i = t >> 4;
    unsigned c = t & 15u;
    unsigned doff = i * 64 + (unsigned)layer * 16 + c;
    const float4* ev = reinterpret_cast<const float4*>(emb);
    reinterpret_cast<float4*>(g_ue)[doff] = ev[(size_t)user[i] * ROW4 + c];
    reinterpret_cast<float4*>(g_pe)[doff] = ev[(size_t)pos [i] * ROW4 + c];
    reinterpret_cast<float4*>(g_ne)[doff] = ev[(size_t)neg [i] * ROW4 + c];
}

__global__ void zero_out_kernel(float* out) {
    if (threadIdx.x == 0 && blockIdx.x == 0) out[0] = 0.f;
}

__global__ void loss_kernel(float* __restrict__ out) {
    int i = blockIdx.x * blockDim.x + threadIdx.x;
    float dp = 0.f, dn = 0.f;
    if (i < BB) {
        const float4* uv = reinterpret_cast<const float4*>(g_ue);
        const float4* pv = reinterpret_cast<const float4*>(g_pe);
        const float4* nv = reinterpret_cast<const float4*>(g_ne);
#pragma unroll 8
        for (int c = 0; c < 64; c++) {
            float4 u = uv[(size_t)i * 64 + c];
            float4 p = pv[(size_t)i * 64 + c];
            float4 q = nv[(size_t)i * 64 + c];
            dp += u.x*p.x + u.y*p.y + u.z*p.z + u.w*p.w;
            dn += u.x*q.x + u.y*q.y + u.z*q.z + u.w*q.w;
        }
    }
    float d = dp - dn;
    float l = (i < BB) ? (fmaxf(-d, 0.f) + log1pf(expf(-fabsf(d)))) : 0.f;

    __shared__ float red[256];
    red[threadIdx.x] = l;
    __syncthreads();
    for (int s = 128; s > 0; s >>= 1) {
        if (threadIdx.x < s) red[threadIdx.x] += red[threadIdx.x + s];
        __syncthreads();
    }
    if (threadIdx.x == 0) atomicAdd(out, red[0]);
}

// ---------------- launch ----------------

extern "C" void kernel_launch(void* const* d_in, const int* in_sizes, int n_in,
                              void* d_out, int out_size) {
    const float* emb  = (const float*)d_in[0];
    const float* w1w  = (const float*)d_in[1];
    const float* w1b  = (const float*)d_in[2];
    const float* w2w  = (const float*)d_in[3];
    const float* w2b  = (const float*)d_in[4];
    const float* vals = (const float*)d_in[5];
    const int*   rows = (const int*)d_in[6];
    const int*   cols = (const int*)d_in[7];
    const int*   user = (const int*)d_in[8];
    const int*   pos  = (const int*)d_in[9];
    const int*   neg  = (const int*)d_in[10];
    float* out = (float*)d_out;

    void *pA = nullptr, *pB = nullptr;
    cudaGetSymbolAddress(&pA, g_embA);
    cudaGetSymbolAddress(&pB, g_embB);
    float* eA = (float*)pA;
    float* eB = (float*)pB;

    const int SMEM_BYTES = DSM_FLOATS * 4;   // 135680
    cudaFuncSetAttribute(dense_kernel,
                         cudaFuncAttributeMaxDynamicSharedMemorySize, SMEM_BYTES);

    const int ZB = (NN * DD / 4 + 255) / 256;
    const int SB = (EE * 16) / 256;           // 78125 exact
    const int DB = (NN + BM - 1) / BM;        // 391
    const int GB = (BB * 16 + 255) / 256;

    // layer 0 input gather
    gather_kernel<<<GB, 256>>>(emb, user, pos, neg, 0);

    // layer 1: emb -> eA
    zero_agg_kernel<<<ZB, 256>>>();
    spmm_kernel<<<SB, 256>>>(emb, vals, rows, cols);
    dense_kernel<<<DB, 256, SMEM_BYTES>>>(emb, w1w, w1b, w2w, w2b, eA);
    gather_kernel<<<GB, 256>>>(eA, user, pos, neg, 1);

    // layer 2: eA -> eB
    zero_agg_kernel<<<ZB, 256>>>();
    spmm_kernel<<<SB, 256>>>(eA, vals, rows, cols);
    dense_kernel<<<DB, 256, SMEM_BYTES>>>(eA, w1w + 4096, w1b + 64, w2w + 4096, w2b + 64, eB);
    gather_kernel<<<GB, 256>>>(eB, user, pos, neg, 2);

    // layer 3: eB -> eA
    zero_agg_kernel<<<ZB, 256>>>();
    spmm_kernel<<<SB, 256>>>(eB, vals, rows, cols);
    dense_kernel<<<DB, 256, SMEM_BYTES>>>(eB, w1w + 8192, w1b + 128, w2w + 8192, w2b + 128, eA);
    gather_kernel<<<GB, 256>>>(eA, user, pos, neg, 3);

    // loss
    zero_out_kernel<<<1, 32>>>(out);
    loss_kernel<<<BB / 256, 256>>>(out);
}